// round 1
// baseline (speedup 1.0000x reference)
#include <cuda_runtime.h>
#include <math.h>

#define T_TOK 1024
#define HID   2048
#define NEXP  16
#define TOPK  4
#define IEXP  1408
#define ISH   2816

// ---------------- scratch (__device__ globals; no allocation allowed) ----------------
__device__ int   g_cnt[NEXP];
__device__ int   g_tok[NEXP * T_TOK];          // per-expert token lists
__device__ int   g_te[T_TOK * TOPK];           // token -> expert ids
__device__ int   g_slot[T_TOK * TOPK];         // token -> slot in expert list
__device__ float g_tw[T_TOK * TOPK];           // token -> renormalized weights
__device__ float g_act[23068672];              // [E][1024][IEXP]  expert silu*up
__device__ float g_ash[2883584];               // [1024][ISH]      shared silu*up
__device__ float g_ysc[33554432];              // [E][1024][HID]   expert down out
__device__ float g_sout[2097152];              // [1024][HID]      shared down out

// ---------------- zero expert counts ----------------
__global__ void zero_kernel() {
    if (threadIdx.x < NEXP) g_cnt[threadIdx.x] = 0;
}

// ---------------- router: logits -> softmax -> top4 -> renorm -> gather ----------------
__global__ void router_kernel(const float* __restrict__ x, const float* __restrict__ Wg) {
    int t = blockIdx.x;
    const float* xr = x + (long)t * HID;
    float acc[NEXP];
#pragma unroll
    for (int e = 0; e < NEXP; e++) acc[e] = 0.f;
    for (int h = threadIdx.x; h < HID; h += 128) {
        float xv = xr[h];
        const float* wr = Wg + (long)h * NEXP;
#pragma unroll
        for (int e = 0; e < NEXP; e++) acc[e] = fmaf(xv, wr[e], acc[e]);
    }
    __shared__ float red[128 * NEXP];
#pragma unroll
    for (int e = 0; e < NEXP; e++) red[threadIdx.x * NEXP + e] = acc[e];
    __syncthreads();
    __shared__ float logits[NEXP];
    if (threadIdx.x < NEXP) {
        float s = 0.f;
        for (int i = 0; i < 128; i++) s += red[i * NEXP + threadIdx.x];
        logits[threadIdx.x] = s;
    }
    __syncthreads();
    if (threadIdx.x == 0) {
        float lv[NEXP];
#pragma unroll
        for (int e = 0; e < NEXP; e++) lv[e] = logits[e];
        int ids[TOPK]; float vals[TOPK];
        bool used[NEXP];
#pragma unroll
        for (int e = 0; e < NEXP; e++) used[e] = false;
        for (int k = 0; k < TOPK; k++) {
            int bi = 0; float bv = -3.4e38f;
            for (int e = 0; e < NEXP; e++)
                if (!used[e] && lv[e] > bv) { bv = lv[e]; bi = e; }
            used[bi] = true; ids[k] = bi; vals[k] = bv;
        }
        float m = vals[0], ssum = 0.f, wv[TOPK];
        for (int k = 0; k < TOPK; k++) { wv[k] = expf(vals[k] - m); ssum += wv[k]; }
        float inv = 1.f / ssum;
        for (int k = 0; k < TOPK; k++) {
            int e = ids[k];
            int slot = atomicAdd(&g_cnt[e], 1);
            g_tok[e * T_TOK + slot] = t;
            g_te[t * TOPK + k]   = e;
            g_slot[t * TOPK + k] = slot;
            g_tw[t * TOPK + k]   = wv[k] * inv;
        }
    }
}

// ---------------- gemm1: (gathered) X @ W^T with fused silu*mul ----------------
// A[rows,K] row-major (K contig), B[2*Ihalf,K] row-major (K contig).
// Block tile: 64 rows x 32 act-cols; computes gate rows [j0,j0+32) and up rows [Ihalf+j0,..).
__global__ void __launch_bounds__(128)
gemm1_kernel(const float* __restrict__ X, const float* __restrict__ Bbase,
             int Ihalf, int K, int shared_mode) {
    int e = blockIdx.z;
    const float* Bp;
    float* act;
    const int* tok;
    int nrows;
    if (shared_mode) {
        Bp = Bbase; act = g_ash; tok = nullptr; nrows = T_TOK;
    } else {
        Bp = Bbase + (long)e * 2 * Ihalf * K;
        act = g_act + (long)e * T_TOK * IEXP;
        tok = g_tok + e * T_TOK;
        nrows = g_cnt[e];
    }
    int row0 = blockIdx.y * 64;
    if (row0 >= nrows) return;
    int j0 = blockIdx.x * 32;

    __shared__ float As[16][65];
    __shared__ float Bg[16][33];
    __shared__ float Bu[16][33];

    int tid = threadIdx.x;
    long aoff[2]; bool aval[2];
#pragma unroll
    for (int i = 0; i < 2; i++) {
        int idx = tid + i * 128;
        int r = idx >> 2, c4 = idx & 3;
        int gr = row0 + r;
        aval[i] = gr < nrows;
        int grow = aval[i] ? (tok ? tok[gr] : gr) : 0;
        aoff[i] = (long)grow * K + c4 * 4;
    }
    int brow = tid >> 2, bc4 = tid & 3;
    long bgoff = (long)(j0 + brow) * K + bc4 * 4;
    long buoff = (long)(Ihalf + j0 + brow) * K + bc4 * 4;

    int tm = tid & 15, tn = tid >> 4;
    float accg[4][4], accu[4][4];
#pragma unroll
    for (int i = 0; i < 4; i++)
#pragma unroll
        for (int j = 0; j < 4; j++) { accg[i][j] = 0.f; accu[i][j] = 0.f; }

    for (int k0 = 0; k0 < K; k0 += 16) {
        float4 av[2];
#pragma unroll
        for (int i = 0; i < 2; i++)
            av[i] = aval[i] ? *(const float4*)(X + aoff[i] + k0) : make_float4(0.f, 0.f, 0.f, 0.f);
        float4 bgv = *(const float4*)(Bp + bgoff + k0);
        float4 buv = *(const float4*)(Bp + buoff + k0);
        __syncthreads();
#pragma unroll
        for (int i = 0; i < 2; i++) {
            int idx = tid + i * 128;
            int r = idx >> 2, c4 = idx & 3;
            As[c4 * 4 + 0][r] = av[i].x;
            As[c4 * 4 + 1][r] = av[i].y;
            As[c4 * 4 + 2][r] = av[i].z;
            As[c4 * 4 + 3][r] = av[i].w;
        }
        Bg[bc4 * 4 + 0][brow] = bgv.x; Bg[bc4 * 4 + 1][brow] = bgv.y;
        Bg[bc4 * 4 + 2][brow] = bgv.z; Bg[bc4 * 4 + 3][brow] = bgv.w;
        Bu[bc4 * 4 + 0][brow] = buv.x; Bu[bc4 * 4 + 1][brow] = buv.y;
        Bu[bc4 * 4 + 2][brow] = buv.z; Bu[bc4 * 4 + 3][brow] = buv.w;
        __syncthreads();
#pragma unroll
        for (int k = 0; k < 16; k++) {
            float a[4], bg[4], bu[4];
#pragma unroll
            for (int i = 0; i < 4; i++) a[i] = As[k][tm * 4 + i];
#pragma unroll
            for (int j = 0; j < 4; j++) { bg[j] = Bg[k][tn * 4 + j]; bu[j] = Bu[k][tn * 4 + j]; }
#pragma unroll
            for (int i = 0; i < 4; i++)
#pragma unroll
                for (int j = 0; j < 4; j++) {
                    accg[i][j] = fmaf(a[i], bg[j], accg[i][j]);
                    accu[i][j] = fmaf(a[i], bu[j], accu[i][j]);
                }
        }
    }
#pragma unroll
    for (int i = 0; i < 4; i++) {
        int gr = row0 + tm * 4 + i;
        if (gr < nrows) {
#pragma unroll
            for (int j = 0; j < 4; j++) {
                float g = accg[i][j], u = accu[i][j];
                float s = g / (1.f + expf(-g));
                act[(long)gr * Ihalf + j0 + tn * 4 + j] = s * u;
            }
        }
    }
}

// ---------------- gemm2: act @ Wdown^T ----------------
// A[rows,K] (K contig), B[N,K] (K contig). Block tile 64x64, thread tile 4x8.
__global__ void __launch_bounds__(128)
gemm2_kernel(const float* __restrict__ Bbase, int N, int K, int shared_mode) {
    int e = blockIdx.z;
    const float* A; const float* B; float* C; int nrows;
    if (shared_mode) {
        A = g_ash; B = Bbase; C = g_sout; nrows = T_TOK;
    } else {
        A = g_act + (long)e * T_TOK * IEXP;
        B = Bbase + (long)e * N * K;
        C = g_ysc + (long)e * T_TOK * HID;
        nrows = g_cnt[e];
    }
    int row0 = blockIdx.y * 64;
    if (row0 >= nrows) return;
    int n0 = blockIdx.x * 64;

    __shared__ float As[16][65];
    __shared__ float Bs[16][65];
    int tid = threadIdx.x;
    long aoff[2]; bool aval[2]; long boff[2];
#pragma unroll
    for (int i = 0; i < 2; i++) {
        int idx = tid + i * 128;
        int r = idx >> 2, c4 = idx & 3;
        int gr = row0 + r;
        aval[i] = gr < nrows;
        aoff[i] = (long)(aval[i] ? gr : 0) * K + c4 * 4;
        boff[i] = (long)(n0 + r) * K + c4 * 4;
    }
    int tm = tid & 15, tn = tid >> 4;
    float acc[4][8];
#pragma unroll
    for (int i = 0; i < 4; i++)
#pragma unroll
        for (int j = 0; j < 8; j++) acc[i][j] = 0.f;

    for (int k0 = 0; k0 < K; k0 += 16) {
        float4 av[2], bv[2];
#pragma unroll
        for (int i = 0; i < 2; i++) {
            av[i] = aval[i] ? *(const float4*)(A + aoff[i] + k0) : make_float4(0.f, 0.f, 0.f, 0.f);
            bv[i] = *(const float4*)(B + boff[i] + k0);
        }
        __syncthreads();
#pragma unroll
        for (int i = 0; i < 2; i++) {
            int idx = tid + i * 128;
            int r = idx >> 2, c4 = idx & 3;
            As[c4 * 4 + 0][r] = av[i].x; As[c4 * 4 + 1][r] = av[i].y;
            As[c4 * 4 + 2][r] = av[i].z; As[c4 * 4 + 3][r] = av[i].w;
            Bs[c4 * 4 + 0][r] = bv[i].x; Bs[c4 * 4 + 1][r] = bv[i].y;
            Bs[c4 * 4 + 2][r] = bv[i].z; Bs[c4 * 4 + 3][r] = bv[i].w;
        }
        __syncthreads();
#pragma unroll
        for (int k = 0; k < 16; k++) {
            float a[4], b[8];
#pragma unroll
            for (int i = 0; i < 4; i++) a[i] = As[k][tm * 4 + i];
#pragma unroll
            for (int j = 0; j < 8; j++) b[j] = Bs[k][tn * 8 + j];
#pragma unroll
            for (int i = 0; i < 4; i++)
#pragma unroll
                for (int j = 0; j < 8; j++) acc[i][j] = fmaf(a[i], b[j], acc[i][j]);
        }
    }
#pragma unroll
    for (int i = 0; i < 4; i++) {
        int gr = row0 + tm * 4 + i;
        if (gr < nrows) {
#pragma unroll
            for (int j = 0; j < 8; j++)
                C[(long)gr * N + n0 + tn * 8 + j] = acc[i][j];
        }
    }
}

// ---------------- combine: out = shared + sum_k w_k * ysc[e_k][slot_k] ----------------
__global__ void combine_kernel(float* __restrict__ out) {
    long idx = (long)blockIdx.x * 256 + threadIdx.x;
    int t = (int)(idx >> 11);   // / HID
    int h = (int)(idx & 2047);  // % HID
    float v = g_sout[idx];
#pragma unroll
    for (int k = 0; k < TOPK; k++) {
        int e = g_te[t * TOPK + k];
        int s = g_slot[t * TOPK + k];
        float w = g_tw[t * TOPK + k];
        v = fmaf(w, g_ysc[((long)e * T_TOK + s) * HID + h], v);
    }
    out[idx] = v;
}

extern "C" void kernel_launch(void* const* d_in, const int* in_sizes, int n_in,
                              void* d_out, int out_size) {
    const float* x   = (const float*)d_in[0];
    const float* Wg  = (const float*)d_in[1];
    const float* W1  = (const float*)d_in[2];
    const float* W2  = (const float*)d_in[3];
    const float* Wsg = (const float*)d_in[4];
    const float* Wsd = (const float*)d_in[5];
    float* out = (float*)d_out;

    zero_kernel<<<1, 32>>>();
    router_kernel<<<T_TOK, 128>>>(x, Wg);

    // shared MLP
    gemm1_kernel<<<dim3(ISH / 32, T_TOK / 64, 1), 128>>>(x, Wsg, ISH, HID, 1);
    gemm2_kernel<<<dim3(HID / 64, T_TOK / 64, 1), 128>>>(Wsd, HID, ISH, 1);

    // expert MLPs (grouped; blocks beyond per-expert row count exit early)
    gemm1_kernel<<<dim3(IEXP / 32, T_TOK / 64, NEXP), 128>>>(x, W1, IEXP, HID, 0);
    gemm2_kernel<<<dim3(HID / 64, T_TOK / 64, NEXP), 128>>>(W2, HID, IEXP, 0);

    combine_kernel<<<(T_TOK * HID) / 256, 256>>>(out);
}

// round 3
// speedup vs baseline: 4.6911x; 4.6911x over previous
#include <cuda_runtime.h>
#include <cuda_fp16.h>
#include <math.h>
#include <stdint.h>

#define T_TOK 1024
#define HID   2048
#define NEXP  16
#define TOPK  4
#define IEXP  1408
#define ISH   2816

// ---------------- scratch (__device__ globals) ----------------
__device__ __align__(1024) __half g_w1h[(size_t)NEXP * 2 * IEXP * HID];
__device__ __align__(1024) __half g_w2h[(size_t)NEXP * HID * IEXP];
__device__ __align__(1024) __half g_wsgh[(size_t)2 * ISH * HID];
__device__ __align__(1024) __half g_wsdh[(size_t)HID * ISH];
__device__ __align__(1024) __half g_xh[(size_t)T_TOK * HID];
__device__ __align__(1024) __half g_xg[(size_t)NEXP * T_TOK * HID];
__device__ __align__(1024) __half g_acth[(size_t)NEXP * T_TOK * IEXP];
__device__ __align__(1024) __half g_ashh[(size_t)T_TOK * ISH];
__device__ float g_ysc[(size_t)NEXP * T_TOK * HID];
__device__ float g_sout[(size_t)T_TOK * HID];
__device__ int   g_cnt[NEXP];
__device__ int   g_te[T_TOK * TOPK];
__device__ int   g_slot[T_TOK * TOPK];
__device__ float g_tw[T_TOK * TOPK];

// ---------------- PTX helpers (plain sm_80-era PTX only; no 'a'-gated features) ----------------
__device__ __forceinline__ uint32_t smem_u32(const void* p) {
    uint32_t a;
    asm("{ .reg .u64 t; cvta.to.shared.u64 t, %1; cvt.u32.u64 %0, t; }" : "=r"(a) : "l"(p));
    return a;
}
#define CP16(dst, src) asm volatile("cp.async.cg.shared.global [%0], [%1], 16;" :: "r"(dst), "l"(src) : "memory")
#define CPCOMMIT()     asm volatile("cp.async.commit_group;" ::: "memory")
#define CPWAIT(n)      asm volatile("cp.async.wait_group %0;" :: "n"(n) : "memory")

__device__ __forceinline__ void ldsm4(uint32_t addr, uint32_t& r0, uint32_t& r1,
                                      uint32_t& r2, uint32_t& r3) {
    asm volatile("ldmatrix.sync.aligned.m8n8.x4.shared.b16 {%0,%1,%2,%3}, [%4];"
                 : "=r"(r0), "=r"(r1), "=r"(r2), "=r"(r3) : "r"(addr));
}
__device__ __forceinline__ void mma16816(float* c, uint32_t a0, uint32_t a1, uint32_t a2,
                                         uint32_t a3, uint32_t b0, uint32_t b1) {
    asm volatile(
        "mma.sync.aligned.m16n8k16.row.col.f32.f16.f16.f32 "
        "{%0,%1,%2,%3}, {%4,%5,%6,%7}, {%8,%9}, {%0,%1,%2,%3};"
        : "+f"(c[0]), "+f"(c[1]), "+f"(c[2]), "+f"(c[3])
        : "r"(a0), "r"(a1), "r"(a2), "r"(a3), "r"(b0), "r"(b1));
}

#define SWZ(o) ((o) ^ (((o) >> 3) & 0x70))
#define NSTAGE 3
#define STAGE_B 32768
#define SMEM_DYN (NSTAGE * STAGE_B + 1024)

// ---------------- fp32 -> fp16 conversion ----------------
__global__ void conv_kernel(const float* __restrict__ src, __half* __restrict__ dst) {
    size_t i = ((size_t)blockIdx.x * 256 + threadIdx.x) * 8;
    float4 a = *(const float4*)(src + i);
    float4 b = *(const float4*)(src + i + 4);
    __half2 h0 = __floats2half2_rn(a.x, a.y), h1 = __floats2half2_rn(a.z, a.w);
    __half2 h2 = __floats2half2_rn(b.x, b.y), h3 = __floats2half2_rn(b.z, b.w);
    uint4 o;
    o.x = *(uint32_t*)&h0; o.y = *(uint32_t*)&h1; o.z = *(uint32_t*)&h2; o.w = *(uint32_t*)&h3;
    *(uint4*)(dst + i) = o;
}

__global__ void zero_kernel() { if (threadIdx.x < NEXP) g_cnt[threadIdx.x] = 0; }

// ---------------- router (fp32, unchanged) ----------------
__global__ void router_kernel(const float* __restrict__ x, const float* __restrict__ Wg) {
    int t = blockIdx.x;
    const float* xr = x + (size_t)t * HID;
    float acc[NEXP];
#pragma unroll
    for (int e = 0; e < NEXP; e++) acc[e] = 0.f;
    for (int h = threadIdx.x; h < HID; h += 128) {
        float xv = xr[h];
        const float* wr = Wg + (size_t)h * NEXP;
#pragma unroll
        for (int e = 0; e < NEXP; e++) acc[e] = fmaf(xv, wr[e], acc[e]);
    }
    __shared__ float red[128 * NEXP];
#pragma unroll
    for (int e = 0; e < NEXP; e++) red[threadIdx.x * NEXP + e] = acc[e];
    __syncthreads();
    __shared__ float logits[NEXP];
    if (threadIdx.x < NEXP) {
        float s = 0.f;
        for (int i = 0; i < 128; i++) s += red[i * NEXP + threadIdx.x];
        logits[threadIdx.x] = s;
    }
    __syncthreads();
    if (threadIdx.x == 0) {
        float lv[NEXP];
#pragma unroll
        for (int e = 0; e < NEXP; e++) lv[e] = logits[e];
        int ids[TOPK]; float vals[TOPK];
        bool used[NEXP];
#pragma unroll
        for (int e = 0; e < NEXP; e++) used[e] = false;
        for (int k = 0; k < TOPK; k++) {
            int bi = 0; float bv = -3.4e38f;
            for (int e = 0; e < NEXP; e++)
                if (!used[e] && lv[e] > bv) { bv = lv[e]; bi = e; }
            used[bi] = true; ids[k] = bi; vals[k] = bv;
        }
        float m = vals[0], ssum = 0.f, wv[TOPK];
        for (int k = 0; k < TOPK; k++) { wv[k] = expf(vals[k] - m); ssum += wv[k]; }
        float inv = 1.f / ssum;
        for (int k = 0; k < TOPK; k++) {
            int e = ids[k];
            int slot = atomicAdd(&g_cnt[e], 1);
            g_te[t * TOPK + k]   = e;
            g_slot[t * TOPK + k] = slot;
            g_tw[t * TOPK + k]   = wv[k] * inv;
        }
    }
}

// ---------------- gather x rows (fp16) into per-expert contiguous buffers ----------------
__global__ void gather_kernel() {
    int b = blockIdx.x;
    int t = b >> 2, k = b & 3;
    int e = g_te[t * TOPK + k], slot = g_slot[t * TOPK + k];
    const uint4* src = (const uint4*)(g_xh + (size_t)t * HID);
    uint4* dst = (uint4*)(g_xg + ((size_t)e * T_TOK + slot) * HID);
    dst[threadIdx.x] = src[threadIdx.x];
}

// ---------------- gemm1 (mma.sync): C[128rows, 64 gate + 64 up] -> silu*mul -> fp16 act ----------------
__global__ void __launch_bounds__(256) gemm1_mma(int shared_mode) {
    int e = blockIdx.z;
    const __half* A; const __half* B; __half* act;
    int nrows, Ihalf;
    const int K = HID;
    if (shared_mode) { A = g_xh; B = g_wsgh; act = g_ashh; nrows = T_TOK; Ihalf = ISH; }
    else {
        A = g_xg + (size_t)e * T_TOK * HID;
        B = g_w1h + (size_t)e * 2 * IEXP * HID;
        act = g_acth + (size_t)e * T_TOK * IEXP;
        nrows = g_cnt[e]; Ihalf = IEXP;
    }
    int m0 = blockIdx.y * 128;
    if (m0 >= nrows) return;
    int j0 = blockIdx.x * 64;

    extern __shared__ char smraw[];
    uint32_t sb = (smem_u32(smraw) + 1023) & ~1023u;
    int tid = threadIdx.x, lane = tid & 31, wid = tid >> 5;

    const __half* asrc[4]; const __half* bsrc[4]; uint32_t swz[4];
#pragma unroll
    for (int i = 0; i < 4; i++) {
        int row = (tid >> 3) + 32 * i;
        int c16 = tid & 7;
        asrc[i] = A + (size_t)(m0 + row) * K + c16 * 8;
        int brow = (row < 64) ? (j0 + row) : (Ihalf + j0 + row - 64);
        bsrc[i] = B + (size_t)brow * K + c16 * 8;
        swz[i] = SWZ((uint32_t)(row * 128 + c16 * 16));
    }

    const int KT = K / 64;
    for (int s = 0; s < NSTAGE - 1; s++) {
        uint32_t sA = sb + s * STAGE_B, sB = sA + 16384;
        int ko = s * 64;
#pragma unroll
        for (int i = 0; i < 4; i++) { CP16(sA + swz[i], asrc[i] + ko); CP16(sB + swz[i], bsrc[i] + ko); }
        CPCOMMIT();
    }

    float ct[16][4];
#pragma unroll
    for (int j = 0; j < 16; j++)
#pragma unroll
        for (int q = 0; q < 4; q++) ct[j][q] = 0.f;

    uint32_t arow = (uint32_t)(wid * 16 + (lane & 15));
    uint32_t kcb = ((lane >> 4) << 3) * 2;   // 0 or 16 bytes

    for (int kt = 0; kt < KT; kt++) {
        CPWAIT(1);
        __syncthreads();
        uint32_t sA = sb + (kt % NSTAGE) * STAGE_B, sB = sA + 16384;
#pragma unroll
        for (int ks = 0; ks < 4; ks++) {
            uint32_t a0, a1, a2, a3;
            ldsm4(sA + SWZ(arow * 128 + ks * 32 + kcb), a0, a1, a2, a3);
#pragma unroll
            for (int nn = 0; nn < 8; nn++) {
                uint32_t b0, b1, b2, b3;
                ldsm4(sB + SWZ((uint32_t)((nn * 16 + (lane & 15)) * 128 + ks * 32 + kcb)), b0, b1, b2, b3);
                mma16816(ct[2 * nn],     a0, a1, a2, a3, b0, b2);
                mma16816(ct[2 * nn + 1], a0, a1, a2, a3, b1, b3);
            }
        }
        __syncthreads();
        int nc = kt + NSTAGE - 1;
        if (nc < KT) {
            uint32_t dA = sb + (nc % NSTAGE) * STAGE_B, dB = dA + 16384;
            int ko = nc * 64;
#pragma unroll
            for (int i = 0; i < 4; i++) { CP16(dA + swz[i], asrc[i] + ko); CP16(dB + swz[i], bsrc[i] + ko); }
        }
        CPCOMMIT();
    }

    // epilogue: ntile j (cols 8j..8j+7) = gate, ntile j+8 = up for same output col
    int row = m0 + wid * 16 + (lane >> 2);
#pragma unroll
    for (int j = 0; j < 8; j++) {
        int col = j0 + j * 8 + (lane & 3) * 2;
        if (row < nrows) {
            float g0 = ct[j][0], g1 = ct[j][1], u0 = ct[j + 8][0], u1 = ct[j + 8][1];
            __half2 h = __floats2half2_rn(g0 / (1.f + expf(-g0)) * u0,
                                          g1 / (1.f + expf(-g1)) * u1);
            *(__half2*)(act + (size_t)row * Ihalf + col) = h;
        }
        if (row + 8 < nrows) {
            float g0 = ct[j][2], g1 = ct[j][3], u0 = ct[j + 8][2], u1 = ct[j + 8][3];
            __half2 h = __floats2half2_rn(g0 / (1.f + expf(-g0)) * u0,
                                          g1 / (1.f + expf(-g1)) * u1);
            *(__half2*)(act + (size_t)(row + 8) * Ihalf + col) = h;
        }
    }
}

// ---------------- gemm2 (mma.sync): C[128,128] = act[128,K] * Wd[128,K]^T -> fp32 ----------------
__global__ void __launch_bounds__(256) gemm2_mma(int shared_mode) {
    int e = blockIdx.z;
    const __half* A; const __half* B; float* C;
    int nrows, K;
    if (shared_mode) { A = g_ashh; B = g_wsdh; C = g_sout; nrows = T_TOK; K = ISH; }
    else {
        A = g_acth + (size_t)e * T_TOK * IEXP;
        B = g_w2h + (size_t)e * HID * IEXP;
        C = g_ysc + (size_t)e * T_TOK * HID;
        nrows = g_cnt[e]; K = IEXP;
    }
    int m0 = blockIdx.y * 128;
    if (m0 >= nrows) return;
    int n0 = blockIdx.x * 128;

    extern __shared__ char smraw[];
    uint32_t sb = (smem_u32(smraw) + 1023) & ~1023u;
    int tid = threadIdx.x, lane = tid & 31, wid = tid >> 5;

    const __half* asrc[4]; const __half* bsrc[4]; uint32_t swz[4];
#pragma unroll
    for (int i = 0; i < 4; i++) {
        int row = (tid >> 3) + 32 * i;
        int c16 = tid & 7;
        asrc[i] = A + (size_t)(m0 + row) * K + c16 * 8;
        bsrc[i] = B + (size_t)(n0 + row) * K + c16 * 8;
        swz[i] = SWZ((uint32_t)(row * 128 + c16 * 16));
    }

    const int KT = K / 64;
    for (int s = 0; s < NSTAGE - 1; s++) {
        uint32_t sA = sb + s * STAGE_B, sB = sA + 16384;
        int ko = s * 64;
#pragma unroll
        for (int i = 0; i < 4; i++) { CP16(sA + swz[i], asrc[i] + ko); CP16(sB + swz[i], bsrc[i] + ko); }
        CPCOMMIT();
    }

    float ct[16][4];
#pragma unroll
    for (int j = 0; j < 16; j++)
#pragma unroll
        for (int q = 0; q < 4; q++) ct[j][q] = 0.f;

    uint32_t arow = (uint32_t)(wid * 16 + (lane & 15));
    uint32_t kcb = ((lane >> 4) << 3) * 2;

    for (int kt = 0; kt < KT; kt++) {
        CPWAIT(1);
        __syncthreads();
        uint32_t sA = sb + (kt % NSTAGE) * STAGE_B, sB = sA + 16384;
#pragma unroll
        for (int ks = 0; ks < 4; ks++) {
            uint32_t a0, a1, a2, a3;
            ldsm4(sA + SWZ(arow * 128 + ks * 32 + kcb), a0, a1, a2, a3);
#pragma unroll
            for (int nn = 0; nn < 8; nn++) {
                uint32_t b0, b1, b2, b3;
                ldsm4(sB + SWZ((uint32_t)((nn * 16 + (lane & 15)) * 128 + ks * 32 + kcb)), b0, b1, b2, b3);
                mma16816(ct[2 * nn],     a0, a1, a2, a3, b0, b2);
                mma16816(ct[2 * nn + 1], a0, a1, a2, a3, b1, b3);
            }
        }
        __syncthreads();
        int nc = kt + NSTAGE - 1;
        if (nc < KT) {
            uint32_t dA = sb + (nc % NSTAGE) * STAGE_B, dB = dA + 16384;
            int ko = nc * 64;
#pragma unroll
            for (int i = 0; i < 4; i++) { CP16(dA + swz[i], asrc[i] + ko); CP16(dB + swz[i], bsrc[i] + ko); }
        }
        CPCOMMIT();
    }

    int row = m0 + wid * 16 + (lane >> 2);
#pragma unroll
    for (int j = 0; j < 16; j++) {
        int col = n0 + j * 8 + (lane & 3) * 2;
        if (row < nrows) {
            float2 v = make_float2(ct[j][0], ct[j][1]);
            *(float2*)(C + (size_t)row * HID + col) = v;
        }
        if (row + 8 < nrows) {
            float2 v = make_float2(ct[j][2], ct[j][3]);
            *(float2*)(C + (size_t)(row + 8) * HID + col) = v;
        }
    }
}

// ---------------- combine ----------------
__global__ void combine_kernel(float* __restrict__ out) {
    size_t idx = (size_t)blockIdx.x * 256 + threadIdx.x;
    int t = (int)(idx >> 11);
    int h = (int)(idx & 2047);
    float v = g_sout[idx];
#pragma unroll
    for (int k = 0; k < TOPK; k++) {
        int e = g_te[t * TOPK + k];
        int s = g_slot[t * TOPK + k];
        float w = g_tw[t * TOPK + k];
        v = fmaf(w, g_ysc[((size_t)e * T_TOK + s) * HID + h], v);
    }
    out[idx] = v;
}

extern "C" void kernel_launch(void* const* d_in, const int* in_sizes, int n_in,
                              void* d_out, int out_size) {
    const float* x   = (const float*)d_in[0];
    const float* Wg  = (const float*)d_in[1];
    const float* W1  = (const float*)d_in[2];
    const float* W2  = (const float*)d_in[3];
    const float* Wsg = (const float*)d_in[4];
    const float* Wsd = (const float*)d_in[5];
    float* out = (float*)d_out;

    cudaFuncSetAttribute(gemm1_mma, cudaFuncAttributeMaxDynamicSharedMemorySize, SMEM_DYN);
    cudaFuncSetAttribute(gemm2_mma, cudaFuncAttributeMaxDynamicSharedMemorySize, SMEM_DYN);

    __half* w1h; __half* w2h; __half* wsgh; __half* wsdh; __half* xh;
    cudaGetSymbolAddress((void**)&w1h, g_w1h);
    cudaGetSymbolAddress((void**)&w2h, g_w2h);
    cudaGetSymbolAddress((void**)&wsgh, g_wsgh);
    cudaGetSymbolAddress((void**)&wsdh, g_wsdh);
    cudaGetSymbolAddress((void**)&xh, g_xh);

    conv_kernel<<<(T_TOK * HID) / 2048, 256>>>(x, xh);
    conv_kernel<<<(NEXP * 2 * IEXP * HID) / 2048, 256>>>(W1, w1h);
    conv_kernel<<<(NEXP * HID * IEXP) / 2048, 256>>>(W2, w2h);
    conv_kernel<<<(2 * ISH * HID) / 2048, 256>>>(Wsg, wsgh);
    conv_kernel<<<(HID * ISH) / 2048, 256>>>(Wsd, wsdh);

    zero_kernel<<<1, 32>>>();
    router_kernel<<<T_TOK, 128>>>(x, Wg);
    gather_kernel<<<T_TOK * TOPK, 256>>>();

    gemm1_mma<<<dim3(IEXP / 64, T_TOK / 128, NEXP), 256, SMEM_DYN>>>(0);
    gemm1_mma<<<dim3(ISH / 64, T_TOK / 128, 1), 256, SMEM_DYN>>>(1);
    gemm2_mma<<<dim3(HID / 128, T_TOK / 128, NEXP), 256, SMEM_DYN>>>(0);
    gemm2_mma<<<dim3(HID / 128, T_TOK / 128, 1), 256, SMEM_DYN>>>(1);

    combine_kernel<<<(T_TOK * HID) / 256, 256>>>(out);
}

// round 4
// speedup vs baseline: 5.6071x; 1.1953x over previous
#include <cuda_runtime.h>
#include <cuda_fp16.h>
#include <math.h>
#include <stdint.h>

#define T_TOK 1024
#define HID   2048
#define NEXP  16
#define TOPK  4
#define IEXP  1408
#define ISH   2816

// ---------------- scratch (__device__ globals) ----------------
__device__ __align__(1024) __half g_w1h[(size_t)NEXP * 2 * IEXP * HID];
__device__ __align__(1024) __half g_w2h[(size_t)NEXP * HID * IEXP];
__device__ __align__(1024) __half g_wsgh[(size_t)2 * ISH * HID];
__device__ __align__(1024) __half g_wsdh[(size_t)HID * ISH];
__device__ __align__(1024) __half g_xh[(size_t)T_TOK * HID];
__device__ __align__(1024) __half g_xg[(size_t)NEXP * T_TOK * HID];
__device__ __align__(1024) __half g_acth[(size_t)NEXP * T_TOK * IEXP];
__device__ __align__(1024) __half g_ashh[(size_t)T_TOK * ISH];
__device__ float g_ysc[(size_t)NEXP * T_TOK * HID];
__device__ float g_sout[(size_t)T_TOK * HID];
__device__ int   g_cnt[NEXP];
__device__ int   g_te[T_TOK * TOPK];
__device__ int   g_slot[T_TOK * TOPK];
__device__ float g_tw[T_TOK * TOPK];

// ---------------- PTX helpers (plain sm_80-era PTX only) ----------------
__device__ __forceinline__ uint32_t smem_u32(const void* p) {
    uint32_t a;
    asm("{ .reg .u64 t; cvta.to.shared.u64 t, %1; cvt.u32.u64 %0, t; }" : "=r"(a) : "l"(p));
    return a;
}
#define CP16(dst, src) asm volatile("cp.async.cg.shared.global [%0], [%1], 16;" :: "r"(dst), "l"(src) : "memory")
#define CPCOMMIT()     asm volatile("cp.async.commit_group;" ::: "memory")
#define CPWAIT(n)      asm volatile("cp.async.wait_group %0;" :: "n"(n) : "memory")

__device__ __forceinline__ void ldsm4(uint32_t addr, uint32_t& r0, uint32_t& r1,
                                      uint32_t& r2, uint32_t& r3) {
    asm volatile("ldmatrix.sync.aligned.m8n8.x4.shared.b16 {%0,%1,%2,%3}, [%4];"
                 : "=r"(r0), "=r"(r1), "=r"(r2), "=r"(r3) : "r"(addr));
}
__device__ __forceinline__ void mma16816(float* c, uint32_t a0, uint32_t a1, uint32_t a2,
                                         uint32_t a3, uint32_t b0, uint32_t b1) {
    asm volatile(
        "mma.sync.aligned.m16n8k16.row.col.f32.f16.f16.f32 "
        "{%0,%1,%2,%3}, {%4,%5,%6,%7}, {%8,%9}, {%0,%1,%2,%3};"
        : "+f"(c[0]), "+f"(c[1]), "+f"(c[2]), "+f"(c[3])
        : "r"(a0), "r"(a1), "r"(a2), "r"(a3), "r"(b0), "r"(b1));
}

#define SWZ(o) ((o) ^ (((o) >> 3) & 0x70))
#define NSTAGE 3
#define STAGE_B 32768
#define SMEM_DYN (NSTAGE * STAGE_B + 1024)

// ---------------- fp32 -> fp16 conversion ----------------
__global__ void conv_kernel(const float* __restrict__ src, __half* __restrict__ dst) {
    size_t i = ((size_t)blockIdx.x * 256 + threadIdx.x) * 8;
    float4 a = *(const float4*)(src + i);
    float4 b = *(const float4*)(src + i + 4);
    __half2 h0 = __floats2half2_rn(a.x, a.y), h1 = __floats2half2_rn(a.z, a.w);
    __half2 h2 = __floats2half2_rn(b.x, b.y), h3 = __floats2half2_rn(b.z, b.w);
    uint4 o;
    o.x = *(uint32_t*)&h0; o.y = *(uint32_t*)&h1; o.z = *(uint32_t*)&h2; o.w = *(uint32_t*)&h3;
    *(uint4*)(dst + i) = o;
}

__global__ void zero_kernel() { if (threadIdx.x < NEXP) g_cnt[threadIdx.x] = 0; }

// ---------------- router (fp32, unchanged) ----------------
__global__ void router_kernel(const float* __restrict__ x, const float* __restrict__ Wg) {
    int t = blockIdx.x;
    const float* xr = x + (size_t)t * HID;
    float acc[NEXP];
#pragma unroll
    for (int e = 0; e < NEXP; e++) acc[e] = 0.f;
    for (int h = threadIdx.x; h < HID; h += 128) {
        float xv = xr[h];
        const float* wr = Wg + (size_t)h * NEXP;
#pragma unroll
        for (int e = 0; e < NEXP; e++) acc[e] = fmaf(xv, wr[e], acc[e]);
    }
    __shared__ float red[128 * NEXP];
#pragma unroll
    for (int e = 0; e < NEXP; e++) red[threadIdx.x * NEXP + e] = acc[e];
    __syncthreads();
    __shared__ float logits[NEXP];
    if (threadIdx.x < NEXP) {
        float s = 0.f;
        for (int i = 0; i < 128; i++) s += red[i * NEXP + threadIdx.x];
        logits[threadIdx.x] = s;
    }
    __syncthreads();
    if (threadIdx.x == 0) {
        float lv[NEXP];
#pragma unroll
        for (int e = 0; e < NEXP; e++) lv[e] = logits[e];
        int ids[TOPK]; float vals[TOPK];
        bool used[NEXP];
#pragma unroll
        for (int e = 0; e < NEXP; e++) used[e] = false;
        for (int k = 0; k < TOPK; k++) {
            int bi = 0; float bv = -3.4e38f;
            for (int e = 0; e < NEXP; e++)
                if (!used[e] && lv[e] > bv) { bv = lv[e]; bi = e; }
            used[bi] = true; ids[k] = bi; vals[k] = bv;
        }
        float m = vals[0], ssum = 0.f, wv[TOPK];
        for (int k = 0; k < TOPK; k++) { wv[k] = expf(vals[k] - m); ssum += wv[k]; }
        float inv = 1.f / ssum;
        for (int k = 0; k < TOPK; k++) {
            int e = ids[k];
            int slot = atomicAdd(&g_cnt[e], 1);
            g_te[t * TOPK + k]   = e;
            g_slot[t * TOPK + k] = slot;
            g_tw[t * TOPK + k]   = wv[k] * inv;
        }
    }
}

// ---------------- gather x rows (fp16) into per-expert contiguous buffers ----------------
__global__ void gather_kernel() {
    int b = blockIdx.x;
    int t = b >> 2, k = b & 3;
    int e = g_te[t * TOPK + k], slot = g_slot[t * TOPK + k];
    const uint4* src = (const uint4*)(g_xh + (size_t)t * HID);
    uint4* dst = (uint4*)(g_xg + ((size_t)e * T_TOK + slot) * HID);
    dst[threadIdx.x] = src[threadIdx.x];
}

// ---------------- gemm1 (mma.sync): C[128rows, 64 gate + 64 up] -> silu*mul -> fp16 act ----------------
// Warp tiling: 4m x 2n. Each warp: rows wm*32..+32, gate cols wn*32..+32 and matching up cols.
__global__ void __launch_bounds__(256) gemm1_mma(int shared_mode) {
    int e = blockIdx.z;
    const __half* A; const __half* B; __half* act;
    int nrows, Ihalf;
    const int K = HID;
    if (shared_mode) { A = g_xh; B = g_wsgh; act = g_ashh; nrows = T_TOK; Ihalf = ISH; }
    else {
        A = g_xg + (size_t)e * T_TOK * HID;
        B = g_w1h + (size_t)e * 2 * IEXP * HID;
        act = g_acth + (size_t)e * T_TOK * IEXP;
        nrows = g_cnt[e]; Ihalf = IEXP;
    }
    int m0 = blockIdx.y * 128;
    if (m0 >= nrows) return;
    int j0 = blockIdx.x * 64;

    extern __shared__ char smraw[];
    uint32_t sb = (smem_u32(smraw) + 1023) & ~1023u;
    int tid = threadIdx.x, lane = tid & 31, wid = tid >> 5;
    int wm = wid & 3, wn = wid >> 2;

    const __half* asrc[4]; const __half* bsrc[4]; uint32_t swz[4];
#pragma unroll
    for (int i = 0; i < 4; i++) {
        int row = (tid >> 3) + 32 * i;
        int c16 = tid & 7;
        asrc[i] = A + (size_t)(m0 + row) * K + c16 * 8;
        int brow = (row < 64) ? (j0 + row) : (Ihalf + j0 + row - 64);
        bsrc[i] = B + (size_t)brow * K + c16 * 8;
        swz[i] = SWZ((uint32_t)(row * 128 + c16 * 16));
    }

    const int KT = K / 64;
    for (int s = 0; s < NSTAGE - 1; s++) {
        uint32_t sA = sb + s * STAGE_B, sB = sA + 16384;
        int ko = s * 64;
#pragma unroll
        for (int i = 0; i < 4; i++) { CP16(sA + swz[i], asrc[i] + ko); CP16(sB + swz[i], bsrc[i] + ko); }
        CPCOMMIT();
    }

    // ct[mi][ni][4]: ni 0..3 = gate (cols wn*32 + ni*8), ni 4..7 = up (same cols + 64)
    float ct[2][8][4];
#pragma unroll
    for (int mi = 0; mi < 2; mi++)
#pragma unroll
        for (int j = 0; j < 8; j++)
#pragma unroll
            for (int q = 0; q < 4; q++) ct[mi][j][q] = 0.f;

    uint32_t l15 = (uint32_t)(lane & 15);
    uint32_t kcb = ((lane >> 4) << 4);   // 0 or 16 bytes within 32B k-chunk

    for (int kt = 0; kt < KT; kt++) {
        CPWAIT(1);
        __syncthreads();
        uint32_t sA = sb + (kt % NSTAGE) * STAGE_B, sB = sA + 16384;
#pragma unroll
        for (int ks = 0; ks < 4; ks++) {
            uint32_t a0[4], a1[4];
            ldsm4(sA + SWZ((uint32_t)((wm * 32 + l15) * 128) + ks * 32 + kcb), a0[0], a0[1], a0[2], a0[3]);
            ldsm4(sA + SWZ((uint32_t)((wm * 32 + 16 + l15) * 128) + ks * 32 + kcb), a1[0], a1[1], a1[2], a1[3]);
#pragma unroll
            for (int bb = 0; bb < 2; bb++) {   // gate
                uint32_t b0, b1, b2, b3;
                ldsm4(sB + SWZ((uint32_t)((wn * 32 + bb * 16 + l15) * 128) + ks * 32 + kcb), b0, b1, b2, b3);
                mma16816(ct[0][2 * bb],     a0[0], a0[1], a0[2], a0[3], b0, b2);
                mma16816(ct[0][2 * bb + 1], a0[0], a0[1], a0[2], a0[3], b1, b3);
                mma16816(ct[1][2 * bb],     a1[0], a1[1], a1[2], a1[3], b0, b2);
                mma16816(ct[1][2 * bb + 1], a1[0], a1[1], a1[2], a1[3], b1, b3);
            }
#pragma unroll
            for (int bb = 0; bb < 2; bb++) {   // up (B smem rows 64..127)
                uint32_t b0, b1, b2, b3;
                ldsm4(sB + SWZ((uint32_t)((64 + wn * 32 + bb * 16 + l15) * 128) + ks * 32 + kcb), b0, b1, b2, b3);
                mma16816(ct[0][4 + 2 * bb],     a0[0], a0[1], a0[2], a0[3], b0, b2);
                mma16816(ct[0][4 + 2 * bb + 1], a0[0], a0[1], a0[2], a0[3], b1, b3);
                mma16816(ct[1][4 + 2 * bb],     a1[0], a1[1], a1[2], a1[3], b0, b2);
                mma16816(ct[1][4 + 2 * bb + 1], a1[0], a1[1], a1[2], a1[3], b1, b3);
            }
        }
        __syncthreads();
        int nc = kt + NSTAGE - 1;
        if (nc < KT) {
            uint32_t dA = sb + (nc % NSTAGE) * STAGE_B, dB = dA + 16384;
            int ko = nc * 64;
#pragma unroll
            for (int i = 0; i < 4; i++) { CP16(dA + swz[i], asrc[i] + ko); CP16(dB + swz[i], bsrc[i] + ko); }
        }
        CPCOMMIT();
    }

    // epilogue: fuse silu(gate)*up in registers
#pragma unroll
    for (int mi = 0; mi < 2; mi++) {
        int row = m0 + wm * 32 + mi * 16 + (lane >> 2);
#pragma unroll
        for (int ni = 0; ni < 4; ni++) {
            int col = j0 + wn * 32 + ni * 8 + (lane & 3) * 2;
            if (row < nrows) {
                float g0 = ct[mi][ni][0], g1 = ct[mi][ni][1];
                float u0 = ct[mi][ni + 4][0], u1 = ct[mi][ni + 4][1];
                __half2 h = __floats2half2_rn(g0 / (1.f + expf(-g0)) * u0,
                                              g1 / (1.f + expf(-g1)) * u1);
                *(__half2*)(act + (size_t)row * Ihalf + col) = h;
            }
            if (row + 8 < nrows) {
                float g0 = ct[mi][ni][2], g1 = ct[mi][ni][3];
                float u0 = ct[mi][ni + 4][2], u1 = ct[mi][ni + 4][3];
                __half2 h = __floats2half2_rn(g0 / (1.f + expf(-g0)) * u0,
                                              g1 / (1.f + expf(-g1)) * u1);
                *(__half2*)(act + (size_t)(row + 8) * Ihalf + col) = h;
            }
        }
    }
}

// ---------------- gemm2 (mma.sync): C[128,128] = act[128,K] * Wd[128,K]^T -> fp32 ----------------
__global__ void __launch_bounds__(256) gemm2_mma(int shared_mode) {
    int e = blockIdx.z;
    const __half* A; const __half* B; float* C;
    int nrows, K;
    if (shared_mode) { A = g_ashh; B = g_wsdh; C = g_sout; nrows = T_TOK; K = ISH; }
    else {
        A = g_acth + (size_t)e * T_TOK * IEXP;
        B = g_w2h + (size_t)e * HID * IEXP;
        C = g_ysc + (size_t)e * T_TOK * HID;
        nrows = g_cnt[e]; K = IEXP;
    }
    int m0 = blockIdx.y * 128;
    if (m0 >= nrows) return;
    int n0 = blockIdx.x * 128;

    extern __shared__ char smraw[];
    uint32_t sb = (smem_u32(smraw) + 1023) & ~1023u;
    int tid = threadIdx.x, lane = tid & 31, wid = tid >> 5;
    int wm = wid & 3, wn = wid >> 2;

    const __half* asrc[4]; const __half* bsrc[4]; uint32_t swz[4];
#pragma unroll
    for (int i = 0; i < 4; i++) {
        int row = (tid >> 3) + 32 * i;
        int c16 = tid & 7;
        asrc[i] = A + (size_t)(m0 + row) * K + c16 * 8;
        bsrc[i] = B + (size_t)(n0 + row) * K + c16 * 8;
        swz[i] = SWZ((uint32_t)(row * 128 + c16 * 16));
    }

    const int KT = K / 64;
    for (int s = 0; s < NSTAGE - 1; s++) {
        uint32_t sA = sb + s * STAGE_B, sB = sA + 16384;
        int ko = s * 64;
#pragma unroll
        for (int i = 0; i < 4; i++) { CP16(sA + swz[i], asrc[i] + ko); CP16(sB + swz[i], bsrc[i] + ko); }
        CPCOMMIT();
    }

    float ct[2][8][4];
#pragma unroll
    for (int mi = 0; mi < 2; mi++)
#pragma unroll
        for (int j = 0; j < 8; j++)
#pragma unroll
            for (int q = 0; q < 4; q++) ct[mi][j][q] = 0.f;

    uint32_t l15 = (uint32_t)(lane & 15);
    uint32_t kcb = ((lane >> 4) << 4);

    for (int kt = 0; kt < KT; kt++) {
        CPWAIT(1);
        __syncthreads();
        uint32_t sA = sb + (kt % NSTAGE) * STAGE_B, sB = sA + 16384;
#pragma unroll
        for (int ks = 0; ks < 4; ks++) {
            uint32_t a0[4], a1[4];
            ldsm4(sA + SWZ((uint32_t)((wm * 32 + l15) * 128) + ks * 32 + kcb), a0[0], a0[1], a0[2], a0[3]);
            ldsm4(sA + SWZ((uint32_t)((wm * 32 + 16 + l15) * 128) + ks * 32 + kcb), a1[0], a1[1], a1[2], a1[3]);
#pragma unroll
            for (int bb = 0; bb < 4; bb++) {
                uint32_t b0, b1, b2, b3;
                ldsm4(sB + SWZ((uint32_t)((wn * 64 + bb * 16 + l15) * 128) + ks * 32 + kcb), b0, b1, b2, b3);
                mma16816(ct[0][2 * bb],     a0[0], a0[1], a0[2], a0[3], b0, b2);
                mma16816(ct[0][2 * bb + 1], a0[0], a0[1], a0[2], a0[3], b1, b3);
                mma16816(ct[1][2 * bb],     a1[0], a1[1], a1[2], a1[3], b0, b2);
                mma16816(ct[1][2 * bb + 1], a1[0], a1[1], a1[2], a1[3], b1, b3);
            }
        }
        __syncthreads();
        int nc = kt + NSTAGE - 1;
        if (nc < KT) {
            uint32_t dA = sb + (nc % NSTAGE) * STAGE_B, dB = dA + 16384;
            int ko = nc * 64;
#pragma unroll
            for (int i = 0; i < 4; i++) { CP16(dA + swz[i], asrc[i] + ko); CP16(dB + swz[i], bsrc[i] + ko); }
        }
        CPCOMMIT();
    }

#pragma unroll
    for (int mi = 0; mi < 2; mi++) {
        int row = m0 + wm * 32 + mi * 16 + (lane >> 2);
#pragma unroll
        for (int ni = 0; ni < 8; ni++) {
            int col = n0 + wn * 64 + ni * 8 + (lane & 3) * 2;
            if (row < nrows)
                *(float2*)(C + (size_t)row * HID + col) = make_float2(ct[mi][ni][0], ct[mi][ni][1]);
            if (row + 8 < nrows)
                *(float2*)(C + (size_t)(row + 8) * HID + col) = make_float2(ct[mi][ni][2], ct[mi][ni][3]);
        }
    }
}

// ---------------- combine ----------------
__global__ void combine_kernel(float* __restrict__ out) {
    size_t idx = (size_t)blockIdx.x * 256 + threadIdx.x;
    int t = (int)(idx >> 11);
    int h = (int)(idx & 2047);
    float v = g_sout[idx];
#pragma unroll
    for (int k = 0; k < TOPK; k++) {
        int e = g_te[t * TOPK + k];
        int s = g_slot[t * TOPK + k];
        float w = g_tw[t * TOPK + k];
        v = fmaf(w, g_ysc[((size_t)e * T_TOK + s) * HID + h], v);
    }
    out[idx] = v;
}

extern "C" void kernel_launch(void* const* d_in, const int* in_sizes, int n_in,
                              void* d_out, int out_size) {
    const float* x   = (const float*)d_in[0];
    const float* Wg  = (const float*)d_in[1];
    const float* W1  = (const float*)d_in[2];
    const float* W2  = (const float*)d_in[3];
    const float* Wsg = (const float*)d_in[4];
    const float* Wsd = (const float*)d_in[5];
    float* out = (float*)d_out;

    cudaFuncSetAttribute(gemm1_mma, cudaFuncAttributeMaxDynamicSharedMemorySize, SMEM_DYN);
    cudaFuncSetAttribute(gemm2_mma, cudaFuncAttributeMaxDynamicSharedMemorySize, SMEM_DYN);

    __half* w1h; __half* w2h; __half* wsgh; __half* wsdh; __half* xh;
    cudaGetSymbolAddress((void**)&w1h, g_w1h);
    cudaGetSymbolAddress((void**)&w2h, g_w2h);
    cudaGetSymbolAddress((void**)&wsgh, g_wsgh);
    cudaGetSymbolAddress((void**)&wsdh, g_wsdh);
    cudaGetSymbolAddress((void**)&xh, g_xh);

    // Launch order chosen so ncu (-s 5 -c 1) captures gemm1_mma (experts) at index 5.
    conv_kernel<<<(T_TOK * HID) / 2048, 256>>>(x, xh);                       // 0
    zero_kernel<<<1, 32>>>();                                                // 1
    router_kernel<<<T_TOK, 128>>>(x, Wg);                                    // 2
    gather_kernel<<<T_TOK * TOPK, 256>>>();                                  // 3
    conv_kernel<<<(NEXP * 2 * IEXP * HID) / 2048, 256>>>(W1, w1h);           // 4
    gemm1_mma<<<dim3(IEXP / 64, T_TOK / 128, NEXP), 256, SMEM_DYN>>>(0);     // 5 <- profiled
    conv_kernel<<<(2 * ISH * HID) / 2048, 256>>>(Wsg, wsgh);                 // 6
    gemm1_mma<<<dim3(ISH / 64, T_TOK / 128, 1), 256, SMEM_DYN>>>(1);         // 7
    conv_kernel<<<(NEXP * HID * IEXP) / 2048, 256>>>(W2, w2h);               // 8
    gemm2_mma<<<dim3(HID / 128, T_TOK / 128, NEXP), 256, SMEM_DYN>>>(0);     // 9
    conv_kernel<<<(HID * ISH) / 2048, 256>>>(Wsd, wsdh);                     // 10
    gemm2_mma<<<dim3(HID / 128, T_TOK / 128, 1), 256, SMEM_DYN>>>(1);        // 11
    combine_kernel<<<(T_TOK * HID) / 256, 256>>>(out);                       // 12
}